// round 3
// baseline (speedup 1.0000x reference)
#include <cuda_runtime.h>
#include <math.h>

// InfoNCE loss: B=131072 rows, D=512 fp32.
// loss = mean_i log(1 + exp((neg_i - pos_i)/T))
// 768 MB streamed once -> HBM-bound. One warp per row, persistent grid-stride
// over rows (removes ~13 wave transitions of the 16384-CTA launch).

#define D 512
#define TEMPERATURE 1.5f
#define NUM_SMS 148
#define CTAS_PER_SM 8

__global__ void __launch_bounds__(256, 8)
infonce_kernel(const float* __restrict__ a,
               const float* __restrict__ p,
               const float* __restrict__ n,
               float* __restrict__ out,
               int B, float invB)
{
    const int lane = threadIdx.x & 31;
    const int warp_in_grid = (int)((blockIdx.x * (unsigned)blockDim.x + threadIdx.x) >> 5);
    const int warps_total = (int)((gridDim.x * blockDim.x) >> 5);

    float acc = 0.f;  // per-thread accumulated loss contribution

    for (int row = warp_in_grid; row < B; row += warps_total) {
        const size_t row_off = (size_t)row * D;
        const float4* __restrict__ a4 = (const float4*)(a + row_off);
        const float4* __restrict__ p4 = (const float4*)(p + row_off);
        const float4* __restrict__ n4 = (const float4*)(n + row_off);

        float aa = 0.f, pp = 0.f, nn = 0.f, ap = 0.f, an = 0.f;

        #pragma unroll
        for (int k = 0; k < 4; ++k) {
            const int idx = lane + 32 * k;
            float4 va = a4[idx];
            float4 vp = p4[idx];
            float4 vn = n4[idx];
            aa = fmaf(va.x, va.x, fmaf(va.y, va.y, fmaf(va.z, va.z, fmaf(va.w, va.w, aa))));
            pp = fmaf(vp.x, vp.x, fmaf(vp.y, vp.y, fmaf(vp.z, vp.z, fmaf(vp.w, vp.w, pp))));
            nn = fmaf(vn.x, vn.x, fmaf(vn.y, vn.y, fmaf(vn.z, vn.z, fmaf(vn.w, vn.w, nn))));
            ap = fmaf(va.x, vp.x, fmaf(va.y, vp.y, fmaf(va.z, vp.z, fmaf(va.w, vp.w, ap))));
            an = fmaf(va.x, vn.x, fmaf(va.y, vn.y, fmaf(va.z, vn.z, fmaf(va.w, vn.w, an))));
        }

        // Warp tree-reduction of the 5 partial sums.
        #pragma unroll
        for (int off = 16; off > 0; off >>= 1) {
            aa += __shfl_xor_sync(0xFFFFFFFFu, aa, off);
            pp += __shfl_xor_sync(0xFFFFFFFFu, pp, off);
            nn += __shfl_xor_sync(0xFFFFFFFFu, nn, off);
            ap += __shfl_xor_sync(0xFFFFFFFFu, ap, off);
            an += __shfl_xor_sync(0xFFFFFFFFu, an, off);
        }

        if (lane == 0) {
            const float na  = fmaxf(sqrtf(aa), 1e-12f);
            const float npo = fmaxf(sqrtf(pp), 1e-12f);
            const float nne = fmaxf(sqrtf(nn), 1e-12f);
            const float pos = ap / (na * npo);
            const float neg = an / (na * nne);
            const float z = (neg - pos) * (1.0f / TEMPERATURE);
            // -log_softmax[0] = log(1 + exp(z)); z in [-1.34, 1.34] -> no overflow
            acc += log1pf(expf(z)) * invB;
        }
    }

    // Block reduction (8 warps, lane-0 partials) then one atomic per CTA.
    __shared__ float s[8];
    const int wid = threadIdx.x >> 5;
    if (lane == 0) s[wid] = acc;
    __syncthreads();
    if (threadIdx.x == 0) {
        float sum = s[0];
        #pragma unroll
        for (int i = 1; i < 8; ++i) sum += s[i];
        atomicAdd(out, sum);
    }
}

extern "C" void kernel_launch(void* const* d_in, const int* in_sizes, int n_in,
                              void* d_out, int out_size)
{
    const float* anchors   = (const float*)d_in[0];
    const float* positives = (const float*)d_in[1];
    const float* negatives = (const float*)d_in[2];
    float* out = (float*)d_out;

    const int B = in_sizes[0] / D;

    cudaMemsetAsync(out, 0, sizeof(float));

    const int threads = 256;                 // 8 warps per CTA
    const int blocks  = NUM_SMS * CTAS_PER_SM;  // persistent: 1184 CTAs
    infonce_kernel<<<blocks, threads>>>(anchors, positives, negatives, out,
                                        B, 1.0f / (float)B);
}

// round 4
// speedup vs baseline: 1.0733x; 1.0733x over previous
#include <cuda_runtime.h>
#include <math.h>

// InfoNCE loss: B=131072 rows, D=512 fp32.
// loss = mean_i log(1 + exp((neg_i - pos_i)/T))
// 768 MB streamed once -> HBM-bound. One warp per row, one CTA per 8 rows.
// 64 regs/thread (occ cap 4) so all 12 float4 loads per warp batch up front
// (MLP_p1 = 12) instead of fragmenting under a 32-reg cap.

#define D 512
#define TEMPERATURE 1.5f

__global__ void __launch_bounds__(256, 4)
infonce_kernel(const float* __restrict__ a,
               const float* __restrict__ p,
               const float* __restrict__ n,
               float* __restrict__ out,
               int B, float invB)
{
    const int warp_global = (int)((blockIdx.x * (unsigned)blockDim.x + threadIdx.x) >> 5);
    const int lane = threadIdx.x & 31;

    float aa = 0.f, pp = 0.f, nn = 0.f, ap = 0.f, an = 0.f;

    if (warp_global < B) {
        const size_t row_off = (size_t)warp_global * D;
        const float4* __restrict__ a4 = (const float4*)(a + row_off);
        const float4* __restrict__ p4 = (const float4*)(p + row_off);
        const float4* __restrict__ n4 = (const float4*)(n + row_off);

        // Batch ALL 12 float4 loads up front: 48 data regs live, fits in the
        // 64-reg budget. 12 back-to-back LDG.128 per lane = high MLP.
        float4 va[4], vp[4], vn[4];
        #pragma unroll
        for (int k = 0; k < 4; ++k) va[k] = a4[lane + 32 * k];
        #pragma unroll
        for (int k = 0; k < 4; ++k) vp[k] = p4[lane + 32 * k];
        #pragma unroll
        for (int k = 0; k < 4; ++k) vn[k] = n4[lane + 32 * k];

        #pragma unroll
        for (int k = 0; k < 4; ++k) {
            aa = fmaf(va[k].x, va[k].x, fmaf(va[k].y, va[k].y, fmaf(va[k].z, va[k].z, fmaf(va[k].w, va[k].w, aa))));
            pp = fmaf(vp[k].x, vp[k].x, fmaf(vp[k].y, vp[k].y, fmaf(vp[k].z, vp[k].z, fmaf(vp[k].w, vp[k].w, pp))));
            nn = fmaf(vn[k].x, vn[k].x, fmaf(vn[k].y, vn[k].y, fmaf(vn[k].z, vn[k].z, fmaf(vn[k].w, vn[k].w, nn))));
            ap = fmaf(va[k].x, vp[k].x, fmaf(va[k].y, vp[k].y, fmaf(va[k].z, vp[k].z, fmaf(va[k].w, vp[k].w, ap))));
            an = fmaf(va[k].x, vn[k].x, fmaf(va[k].y, vn[k].y, fmaf(va[k].z, vn[k].z, fmaf(va[k].w, vn[k].w, an))));
        }
    }

    // Warp tree-reduction of the 5 partial sums.
    #pragma unroll
    for (int off = 16; off > 0; off >>= 1) {
        aa += __shfl_xor_sync(0xFFFFFFFFu, aa, off);
        pp += __shfl_xor_sync(0xFFFFFFFFu, pp, off);
        nn += __shfl_xor_sync(0xFFFFFFFFu, nn, off);
        ap += __shfl_xor_sync(0xFFFFFFFFu, ap, off);
        an += __shfl_xor_sync(0xFFFFFFFFu, an, off);
    }

    float partial = 0.f;
    if (lane == 0 && warp_global < B) {
        const float na  = fmaxf(sqrtf(aa), 1e-12f);
        const float npo = fmaxf(sqrtf(pp), 1e-12f);
        const float nne = fmaxf(sqrtf(nn), 1e-12f);
        const float pos = ap / (na * npo);
        const float neg = an / (na * nne);
        const float z = (neg - pos) * (1.0f / TEMPERATURE);
        // -log_softmax[0] = log(1 + exp(z)); z in [-1.34, 1.34] -> no overflow
        partial = log1pf(expf(z)) * invB;
    }

    // Block reduction (8 warps) then a single atomic per block.
    __shared__ float s[8];
    const int wid = threadIdx.x >> 5;
    if (lane == 0) s[wid] = partial;
    __syncthreads();
    if (threadIdx.x == 0) {
        float sum = s[0];
        #pragma unroll
        for (int i = 1; i < 8; ++i) sum += s[i];
        atomicAdd(out, sum);
    }
}

extern "C" void kernel_launch(void* const* d_in, const int* in_sizes, int n_in,
                              void* d_out, int out_size)
{
    const float* anchors   = (const float*)d_in[0];
    const float* positives = (const float*)d_in[1];
    const float* negatives = (const float*)d_in[2];
    float* out = (float*)d_out;

    const int B = in_sizes[0] / D;

    cudaMemsetAsync(out, 0, sizeof(float));

    const int threads = 256;               // 8 warps = 8 rows per block
    const int blocks = (B + 7) / 8;
    infonce_kernel<<<blocks, threads>>>(anchors, positives, negatives, out,
                                        B, 1.0f / (float)B);
}